// round 7
// baseline (speedup 1.0000x reference)
#include <cuda_runtime.h>
#include <math.h>

#define FLOW_SZ 1048576       // 2*2*512*512

// ---- device scratch (filled by upsample kernel's prep blocks) ----
__device__ __align__(16) float g_w1t[81 * 64];     // g_w1t[c*64+o] = fte_w1[o*81+c]
__device__ __align__(16) float g_w2t[64 * 64];     // g_w2t[c*64+o] = fte_w2[o*64+c]
__device__ __align__(16) float g_wk_t[64 * 128];   // g_wk_t[d*128+c] = wk[c*64+d]

__device__ __forceinline__ float gelu_exact(float x) {
    return 0.5f * x * (1.0f + erff(x * 0.70710678118654752f));
}

__device__ __forceinline__ float samp_map(const float* __restrict__ p, int ix, int iy) {
    if ((unsigned)ix < 64u && (unsigned)iy < 64u) return p[iy * 64 + ix];
    return 0.0f;
}

__device__ __forceinline__ float4 fma4(float s, float4 a, float4 b) {
    return make_float4(fmaf(s, a.x, b.x), fmaf(s, a.y, b.y),
                       fmaf(s, a.z, b.z), fmaf(s, a.w, b.w));
}
__device__ __forceinline__ float4 fma44(float4 m, float4 a, float4 b) {
    return make_float4(fmaf(m.x, a.x, b.x), fmaf(m.y, a.y, b.y),
                       fmaf(m.z, a.z, b.z), fmaf(m.w, a.w, b.w));
}
__device__ __forceinline__ float hsum4(float4 a) {
    return (a.x + a.y) + (a.z + a.w);
}

__device__ __forceinline__ float posenc(float cx, float cy, int o) {
    int r = o >> 4, f = o & 15;
    float base = (r < 2) ? cx : cy;
    float ang = 3.14f * base * (float)f / 200.0f;
    return ((r & 1) == 0) ? sinf(ang) : cosf(ang);
}

// Quad-token matmul: out[t][o] = sum_c act[t][c] * w[c*64+o], o0=2*lane, o1=2*lane+1.
// Weight rows loaded once (LDG.64) and shared across 4 tokens; activations are
// broadcast LDS.128 (1 per 4 rows per token). ROWS % 4 == 0.
template <int ROWS>
__device__ __forceinline__ void mm4(const float* a0, const float* a1,
                                    const float* a2, const float* a3,
                                    const float* __restrict__ w, int l,
                                    float2& r0, float2& r1,
                                    float2& r2, float2& r3)
{
    const float* wl = w + 2 * l;
    #pragma unroll 4
    for (int c = 0; c < ROWS; c += 4) {
        float4 x0 = *(const float4*)(a0 + c);
        float4 x1 = *(const float4*)(a1 + c);
        float4 x2 = *(const float4*)(a2 + c);
        float4 x3 = *(const float4*)(a3 + c);
        float2 wa = *(const float2*)(wl + (c + 0) * 64);
        float2 wb = *(const float2*)(wl + (c + 1) * 64);
        float2 wc = *(const float2*)(wl + (c + 2) * 64);
        float2 wd = *(const float2*)(wl + (c + 3) * 64);
        r0.x = fmaf(x0.x, wa.x, r0.x); r0.y = fmaf(x0.x, wa.y, r0.y);
        r1.x = fmaf(x1.x, wa.x, r1.x); r1.y = fmaf(x1.x, wa.y, r1.y);
        r2.x = fmaf(x2.x, wa.x, r2.x); r2.y = fmaf(x2.x, wa.y, r2.y);
        r3.x = fmaf(x3.x, wa.x, r3.x); r3.y = fmaf(x3.x, wa.y, r3.y);
        r0.x = fmaf(x0.y, wb.x, r0.x); r0.y = fmaf(x0.y, wb.y, r0.y);
        r1.x = fmaf(x1.y, wb.x, r1.x); r1.y = fmaf(x1.y, wb.y, r1.y);
        r2.x = fmaf(x2.y, wb.x, r2.x); r2.y = fmaf(x2.y, wb.y, r2.y);
        r3.x = fmaf(x3.y, wb.x, r3.x); r3.y = fmaf(x3.y, wb.y, r3.y);
        r0.x = fmaf(x0.z, wc.x, r0.x); r0.y = fmaf(x0.z, wc.y, r0.y);
        r1.x = fmaf(x1.z, wc.x, r1.x); r1.y = fmaf(x1.z, wc.y, r1.y);
        r2.x = fmaf(x2.z, wc.x, r2.x); r2.y = fmaf(x2.z, wc.y, r2.y);
        r3.x = fmaf(x3.z, wc.x, r3.x); r3.y = fmaf(x3.z, wc.y, r3.y);
        r0.x = fmaf(x0.w, wd.x, r0.x); r0.y = fmaf(x0.w, wd.y, r0.y);
        r1.x = fmaf(x1.w, wd.x, r1.x); r1.y = fmaf(x1.w, wd.y, r1.y);
        r2.x = fmaf(x2.w, wd.x, r2.x); r2.y = fmaf(x2.w, wd.y, r2.y);
        r3.x = fmaf(x3.w, wd.x, r3.x); r3.y = fmaf(x3.w, wd.y, r3.y);
    }
}

// Per-block (one warp) shared state for 4 tokens. Rows of cm/tu padded to
// 132 floats (16B-aligned, 4-bank rotation per row) for conflict-free access.
struct __align__(16) WarpSmem {
    float cm[4][1056];    // 8 x 132 cost_memory rows per token
    float tu[4][1056];    // t[h][c] then overwritten by u[h][c]
    float corr[4][88];    // 81 correlation values
    float attn[4][64];    // softmaxed attention
    float qlin[4][64];
    float A[4][64];       // gelu(fte1) -> attn_out -> ffn hidden
    float B[4][64];       // normed (+enc) vectors
    float sh[4][64];      // short (residual)
    float xs[4][64];      // final
};

__global__ __launch_bounds__(32) void decoder_kernel(
    const float* __restrict__ cost_maps,
    const float* __restrict__ cost_memory,
    const float* __restrict__ coords1,
    const float* __restrict__ fte_b1,
    const float* __restrict__ fte_b2,
    const float* __restrict__ ln1_g, const float* __restrict__ ln1_b,
    const float* __restrict__ ln2_g, const float* __restrict__ ln2_b,
    const float* __restrict__ wq,  const float* __restrict__ bq,
    const float* __restrict__ wv,  const float* __restrict__ bv,
    const float* __restrict__ wp,  const float* __restrict__ bp,
    const float* __restrict__ fw1, const float* __restrict__ fb1,
    const float* __restrict__ fw2, const float* __restrict__ fb2,
    float* __restrict__ out)
{
    __shared__ WarpSmem S;
    const int l = threadIdx.x;
    const int n0 = blockIdx.x * 4;      // tokens n0 .. n0+3 (never cross batch)
    const int b = n0 >> 12;
    const int pix0 = n0 & 4095;
    const int o0 = 2 * l, o1 = 2 * l + 1;

    float cx[4], cy[4];
    #pragma unroll
    for (int t = 0; t < 4; ++t) {
        cx[t] = coords1[b * 8192 + pix0 + t];
        cy[t] = coords1[b * 8192 + 4096 + pix0 + t];
    }

    // ---- phase 0: load cost_memory rows into padded smem ----
    #pragma unroll
    for (int t = 0; t < 4; ++t) {
        const float4* src = (const float4*)(cost_memory + (size_t)(n0 + t) * 1024);
        #pragma unroll
        for (int r = 0; r < 8; ++r)
            ((float4*)&S.cm[t][r * 132])[l] = src[r * 32 + l];
    }

    // ---- phase 1: bilinear correlation sampling (81 per token) ----
    #pragma unroll
    for (int t = 0; t < 4; ++t) {
        const float* cmap = cost_maps + (size_t)(n0 + t) * 4096;
        for (int s = l; s < 81; s += 32) {
            int si = s / 9, sj = s - si * 9;
            float px = cx[t] + (float)(si - 4);
            float py = cy[t] + (float)(sj - 4);
            float fx0 = floorf(px), fy0 = floorf(py);
            float wx = px - fx0, wy = py - fy0;
            int ix = (int)fx0, iy = (int)fy0;
            float v00 = samp_map(cmap, ix,     iy);
            float v10 = samp_map(cmap, ix + 1, iy);
            float v01 = samp_map(cmap, ix,     iy + 1);
            float v11 = samp_map(cmap, ix + 1, iy + 1);
            S.corr[t][s] = v00 * (1.f - wx) * (1.f - wy) + v10 * wx * (1.f - wy)
                         + v01 * (1.f - wx) * wy         + v11 * wx * wy;
        }
    }
    __syncwarp();

    // ---- phase 2: FTE1 = gelu(corr @ W1 + b1) ----
    {
        float2 bb = *(const float2*)(fte_b1 + o0);
        float2 r0 = bb, r1 = bb, r2 = bb, r3 = bb;
        mm4<80>(S.corr[0], S.corr[1], S.corr[2], S.corr[3], g_w1t, l, r0, r1, r2, r3);
        float2 w80 = *(const float2*)(g_w1t + 80 * 64 + o0);
        float a0 = S.corr[0][80], a1 = S.corr[1][80];
        float a2 = S.corr[2][80], a3 = S.corr[3][80];
        r0.x = fmaf(a0, w80.x, r0.x); r0.y = fmaf(a0, w80.y, r0.y);
        r1.x = fmaf(a1, w80.x, r1.x); r1.y = fmaf(a1, w80.y, r1.y);
        r2.x = fmaf(a2, w80.x, r2.x); r2.y = fmaf(a2, w80.y, r2.y);
        r3.x = fmaf(a3, w80.x, r3.x); r3.y = fmaf(a3, w80.y, r3.y);
        *(float2*)&S.A[0][o0] = make_float2(gelu_exact(r0.x), gelu_exact(r0.y));
        *(float2*)&S.A[1][o0] = make_float2(gelu_exact(r1.x), gelu_exact(r1.y));
        *(float2*)&S.A[2][o0] = make_float2(gelu_exact(r2.x), gelu_exact(r2.y));
        *(float2*)&S.A[3][o0] = make_float2(gelu_exact(r3.x), gelu_exact(r3.y));
    }
    __syncwarp();

    // ---- phase 3: query = A @ W2 + b2 (= short) ----
    float2 q[4];
    {
        float2 bb = *(const float2*)(fte_b2 + o0);
        q[0] = bb; q[1] = bb; q[2] = bb; q[3] = bb;
        mm4<64>(S.A[0], S.A[1], S.A[2], S.A[3], g_w2t, l, q[0], q[1], q[2], q[3]);
        #pragma unroll
        for (int t = 0; t < 4; ++t) *(float2*)&S.sh[t][o0] = q[t];
    }

    // ---- phase 4: layernorm1 + positional encoding ----
    {
        float sm[4], vr[4];
        #pragma unroll
        for (int t = 0; t < 4; ++t) sm[t] = q[t].x + q[t].y;
        #pragma unroll
        for (int off = 16; off; off >>= 1) {
            #pragma unroll
            for (int t = 0; t < 4; ++t)
                sm[t] += __shfl_xor_sync(0xffffffffu, sm[t], off);
        }
        float d[4][2];
        #pragma unroll
        for (int t = 0; t < 4; ++t) {
            float mean = sm[t] * (1.f / 64.f);
            d[t][0] = q[t].x - mean;
            d[t][1] = q[t].y - mean;
            vr[t] = d[t][0] * d[t][0] + d[t][1] * d[t][1];
        }
        #pragma unroll
        for (int off = 16; off; off >>= 1) {
            #pragma unroll
            for (int t = 0; t < 4; ++t)
                vr[t] += __shfl_xor_sync(0xffffffffu, vr[t], off);
        }
        float2 g2 = *(const float2*)(ln1_g + o0);
        float2 b2v = *(const float2*)(ln1_b + o0);
        #pragma unroll
        for (int t = 0; t < 4; ++t) {
            float inv = rsqrtf(vr[t] * (1.f / 64.f) + 1e-5f);
            float e0 = posenc(cx[t], cy[t], o0);
            float e1 = posenc(cx[t], cy[t], o1);
            *(float2*)&S.B[t][o0] = make_float2(d[t][0] * inv * g2.x + b2v.x + e0,
                                                d[t][1] * inv * g2.y + b2v.y + e1);
        }
    }
    __syncwarp();

    // ---- phase 5: qlin = B @ wq + bq ----
    {
        float2 bb = *(const float2*)(bq + o0);
        float2 r0 = bb, r1 = bb, r2 = bb, r3 = bb;
        mm4<64>(S.B[0], S.B[1], S.B[2], S.B[3], wq, l, r0, r1, r2, r3);
        *(float2*)&S.qlin[0][o0] = r0;
        *(float2*)&S.qlin[1][o0] = r1;
        *(float2*)&S.qlin[2][o0] = r2;
        *(float2*)&S.qlin[3][o0] = r3;
    }
    __syncwarp();

    // ---- phase 6: T: t[h][c] = sum_e wk_t[h*8+e][c] * q[h*8+e] (weights shared) ----
    #pragma unroll
    for (int h = 0; h < 8; ++h) {
        float qs[4][8];
        #pragma unroll
        for (int t = 0; t < 4; ++t) {
            *(float4*)&qs[t][0] = *(const float4*)&S.qlin[t][h * 8];
            *(float4*)&qs[t][4] = *(const float4*)&S.qlin[t][h * 8 + 4];
        }
        const float* wbase = g_wk_t + (size_t)(h * 8) * 128 + 4 * l;
        float4 acc0 = make_float4(0.f, 0.f, 0.f, 0.f);
        float4 acc1 = acc0, acc2 = acc0, acc3 = acc0;
        #pragma unroll
        for (int e = 0; e < 8; ++e) {
            float4 w = *(const float4*)(wbase + e * 128);
            acc0 = fma4(qs[0][e], w, acc0);
            acc1 = fma4(qs[1][e], w, acc1);
            acc2 = fma4(qs[2][e], w, acc2);
            acc3 = fma4(qs[3][e], w, acc3);
        }
        *(float4*)&S.tu[0][h * 132 + 4 * l] = acc0;
        *(float4*)&S.tu[1][h * 132 + 4 * l] = acc1;
        *(float4*)&S.tu[2][h * 132 + 4 * l] = acc2;
        *(float4*)&S.tu[3][h * 132 + 4 * l] = acc3;
    }
    __syncwarp();

    // ---- phase 7: scores + softmax (bk cancels in softmax) ----
    {
        const int h0 = l >> 3, j = l & 7, h1 = h0 + 4;
        const float scale = 0.35355339059327373f;
        #pragma unroll
        for (int t = 0; t < 4; ++t) {
            const float4* cmj = (const float4*)&S.cm[t][j * 132];
            const float4* ta  = (const float4*)&S.tu[t][h0 * 132];
            const float4* tb  = (const float4*)&S.tu[t][h1 * 132];
            float4 A0 = make_float4(0.f, 0.f, 0.f, 0.f), A1 = A0;
            #pragma unroll 8
            for (int c4 = 0; c4 < 32; ++c4) {
                float4 m = cmj[c4];
                A0 = fma44(m, ta[c4], A0);
                A1 = fma44(m, tb[c4], A1);
            }
            float s0 = hsum4(A0) * scale;
            float s1 = hsum4(A1) * scale;
            float m0 = s0, m1 = s1;
            #pragma unroll
            for (int off = 4; off; off >>= 1) {
                m0 = fmaxf(m0, __shfl_xor_sync(0xffffffffu, m0, off));
                m1 = fmaxf(m1, __shfl_xor_sync(0xffffffffu, m1, off));
            }
            float e0 = expf(s0 - m0), e1 = expf(s1 - m1);
            float t0 = e0, t1 = e1;
            #pragma unroll
            for (int off = 4; off; off >>= 1) {
                t0 += __shfl_xor_sync(0xffffffffu, t0, off);
                t1 += __shfl_xor_sync(0xffffffffu, t1, off);
            }
            S.attn[t][h0 * 8 + j] = e0 / t0;
            S.attn[t][h1 * 8 + j] = e1 / t1;
        }
    }
    __syncwarp();

    // ---- phase 8: u[h] = sum_j attn[h][j] * cm[j]  (overwrites tu) ----
    #pragma unroll
    for (int t = 0; t < 4; ++t) {
        float4 uacc[8];
        #pragma unroll
        for (int h = 0; h < 8; ++h) uacc[h] = make_float4(0.f, 0.f, 0.f, 0.f);
        #pragma unroll
        for (int j = 0; j < 8; ++j) {
            float4 m = *(const float4*)&S.cm[t][j * 132 + 4 * l];
            #pragma unroll
            for (int h = 0; h < 8; ++h)
                uacc[h] = fma4(S.attn[t][h * 8 + j], m, uacc[h]);
        }
        #pragma unroll
        for (int h = 0; h < 8; ++h)
            *(float4*)&S.tu[t][h * 132 + 4 * l] = uacc[h];
    }
    __syncwarp();

    // ---- phase 9: out = u @ wv + bv  (wv original layout, coalesced) ----
    {
        float2 bb = *(const float2*)(bv + o0);
        float2 r0 = bb, r1 = bb, r2 = bb, r3 = bb;
        const int h = l >> 2;   // head of both o0 and o1
        mm4<128>(&S.tu[0][h * 132], &S.tu[1][h * 132],
                 &S.tu[2][h * 132], &S.tu[3][h * 132], wv, l, r0, r1, r2, r3);
        *(float2*)&S.A[0][o0] = r0;
        *(float2*)&S.A[1][o0] = r1;
        *(float2*)&S.A[2][o0] = r2;
        *(float2*)&S.A[3][o0] = r3;
    }
    __syncwarp();

    // ---- phase 10: x = concat(out, short) @ wp + bp + short ----
    float2 x[4];
    {
        float2 bb = *(const float2*)(bp + o0);
        x[0] = bb; x[1] = bb; x[2] = bb; x[3] = bb;
        mm4<64>(S.A[0], S.A[1], S.A[2], S.A[3], wp, l, x[0], x[1], x[2], x[3]);
        mm4<64>(S.sh[0], S.sh[1], S.sh[2], S.sh[3], wp + 64 * 64, l,
                x[0], x[1], x[2], x[3]);
        #pragma unroll
        for (int t = 0; t < 4; ++t) {
            float2 sh = *(const float2*)&S.sh[t][o0];
            x[t].x += sh.x; x[t].y += sh.y;
        }
    }

    // ---- phase 11: layernorm2 ----
    {
        float sm[4], vr[4];
        #pragma unroll
        for (int t = 0; t < 4; ++t) sm[t] = x[t].x + x[t].y;
        #pragma unroll
        for (int off = 16; off; off >>= 1) {
            #pragma unroll
            for (int t = 0; t < 4; ++t)
                sm[t] += __shfl_xor_sync(0xffffffffu, sm[t], off);
        }
        float d[4][2];
        #pragma unroll
        for (int t = 0; t < 4; ++t) {
            float mean = sm[t] * (1.f / 64.f);
            d[t][0] = x[t].x - mean;
            d[t][1] = x[t].y - mean;
            vr[t] = d[t][0] * d[t][0] + d[t][1] * d[t][1];
        }
        #pragma unroll
        for (int off = 16; off; off >>= 1) {
            #pragma unroll
            for (int t = 0; t < 4; ++t)
                vr[t] += __shfl_xor_sync(0xffffffffu, vr[t], off);
        }
        float2 g2 = *(const float2*)(ln2_g + o0);
        float2 b2v = *(const float2*)(ln2_b + o0);
        #pragma unroll
        for (int t = 0; t < 4; ++t) {
            float inv = rsqrtf(vr[t] * (1.f / 64.f) + 1e-5f);
            *(float2*)&S.B[t][o0] = make_float2(d[t][0] * inv * g2.x + b2v.x,
                                                d[t][1] * inv * g2.y + b2v.y);
        }
    }
    __syncwarp();

    // ---- phase 12: FFN hidden ----
    {
        float2 bb = *(const float2*)(fb1 + o0);
        float2 r0 = bb, r1 = bb, r2 = bb, r3 = bb;
        mm4<64>(S.B[0], S.B[1], S.B[2], S.B[3], fw1, l, r0, r1, r2, r3);
        *(float2*)&S.A[0][o0] = make_float2(gelu_exact(r0.x), gelu_exact(r0.y));
        *(float2*)&S.A[1][o0] = make_float2(gelu_exact(r1.x), gelu_exact(r1.y));
        *(float2*)&S.A[2][o0] = make_float2(gelu_exact(r2.x), gelu_exact(r2.y));
        *(float2*)&S.A[3][o0] = make_float2(gelu_exact(r3.x), gelu_exact(r3.y));
    }
    __syncwarp();

    // ---- phase 13: FFN out + residual ----
    {
        float2 bb = *(const float2*)(fb2 + o0);
        float2 r0 = bb, r1 = bb, r2 = bb, r3 = bb;
        mm4<64>(S.A[0], S.A[1], S.A[2], S.A[3], fw2, l, r0, r1, r2, r3);
        *(float2*)&S.xs[0][o0] = make_float2(x[0].x + r0.x, x[0].y + r0.y);
        *(float2*)&S.xs[1][o0] = make_float2(x[1].x + r1.x, x[1].y + r1.y);
        *(float2*)&S.xs[2][o0] = make_float2(x[2].x + r2.x, x[2].y + r2.y);
        *(float2*)&S.xs[3][o0] = make_float2(x[3].x + r3.x, x[3].y + r3.y);
    }
    __syncwarp();

    // ---- phase 14: transposed writeout, STG.128 of 4 token values per row ----
    {
        float* cg = out + FLOW_SZ + (size_t)b * 64 * 4096 + pix0;
        #pragma unroll
        for (int rep = 0; rep < 2; ++rep) {
            int o = l + rep * 32;
            float4 v = make_float4(S.xs[0][o], S.xs[1][o], S.xs[2][o], S.xs[3][o]);
            *(float4*)(cg + (size_t)o * 4096) = v;
        }
    }
}

// ============================================================================
// Convex upsampling; blocks 0..23 transpose FTE weights, blocks 24..55
// transpose wk for the decoder's T step.
// ============================================================================
__global__ __launch_bounds__(256) void upsample_kernel(
    const float* __restrict__ coords1,
    const float* __restrict__ up_mask,
    const float* __restrict__ fte_w1,
    const float* __restrict__ fte_w2,
    const float* __restrict__ wk,
    float* __restrict__ out)
{
    __shared__ float slab[576 * 8];
    __shared__ float fl[2][3][10];
    __shared__ float outp[2 * 8 * 64];

    int blk = blockIdx.x;
    int tid = threadIdx.x;

    if (blk < 24) {
        int i = blk * 256 + tid;
        if (i < 81 * 64) {
            int c = i >> 6, o = i & 63;
            g_w1t[i] = fte_w1[o * 81 + c];
        }
        if (i < 64 * 64) {
            int c = i >> 6, o = i & 63;
            g_w2t[i] = fte_w2[o * 64 + c];
        }
    } else if (blk < 56) {
        int i = (blk - 24) * 256 + tid;   // [0, 8192)
        int d = i >> 7, c = i & 127;
        g_wk_t[i] = wk[c * 64 + d];
    }

    int b   = blk >> 9;
    int rem = blk & 511;
    int y   = rem >> 3;
    int x0  = (rem & 7) << 3;

    const float* mbase = up_mask + (size_t)b * 576 * 4096 + y * 64 + x0;
    for (int idx = tid; idx < 1152; idx += 256) {
        int ch = idx >> 1, half = idx & 1;
        ((float4*)slab)[idx] =
            *(const float4*)(mbase + (size_t)ch * 4096 + half * 4);
    }
    if (tid < 60) {
        int c = tid / 30, r2 = tid % 30, r = r2 / 10, cc = r2 % 10;
        int yy = y + r - 1, xx = x0 + cc - 1;
        float v = 0.0f;
        if ((unsigned)yy < 64u && (unsigned)xx < 64u) {
            float coord = coords1[b * 8192 + c * 4096 + yy * 64 + xx];
            v = 8.0f * (coord - (float)(c == 0 ? xx : yy));
        }
        fl[c][r][cc] = v;
    }
    __syncthreads();

    for (int q = tid; q < 512; q += 256) {
        int p  = q & 7;
        int ij = q >> 3;
        int i  = ij >> 3, j = ij & 7;
        float w[9];
        float mx = -1e30f;
        #pragma unroll
        for (int kk = 0; kk < 9; ++kk) {
            w[kk] = slab[(kk * 64 + ij) * 8 + p];
            mx = fmaxf(mx, w[kk]);
        }
        float s = 0.f;
        #pragma unroll
        for (int kk = 0; kk < 9; ++kk) { w[kk] = __expf(w[kk] - mx); s += w[kk]; }
        float inv = 1.0f / s;
        float u0 = 0.f, u1 = 0.f;
        #pragma unroll
        for (int kk = 0; kk < 9; ++kk) {
            int dy = kk / 3, dx = kk - dy * 3;
            u0 = fmaf(w[kk], fl[0][dy][p + dx], u0);
            u1 = fmaf(w[kk], fl[1][dy][p + dx], u1);
        }
        int col = p * 8 + j;
        outp[(0 * 8 + i) * 64 + col] = u0 * inv;
        outp[(1 * 8 + i) * 64 + col] = u1 * inv;
    }
    __syncthreads();

    float* obase = out + (size_t)b * 2 * 512 * 512 + (size_t)(8 * y) * 512 + 8 * x0;
    for (int idx = tid; idx < 1024; idx += 256) {
        int c = idx >> 9, rest = idx & 511;
        int i = rest >> 6, col = rest & 63;
        obase[(size_t)c * 512 * 512 + i * 512 + col] = outp[(c * 8 + i) * 64 + col];
    }
}

extern "C" void kernel_launch(void* const* d_in, const int* in_sizes, int n_in,
                              void* d_out, int out_size) {
    const float* cost_maps   = (const float*)d_in[0];
    const float* cost_memory = (const float*)d_in[1];
    const float* coords1     = (const float*)d_in[2];
    const float* up_mask     = (const float*)d_in[3];
    const float* fte_w1      = (const float*)d_in[4];
    const float* fte_b1      = (const float*)d_in[5];
    const float* fte_w2      = (const float*)d_in[6];
    const float* fte_b2      = (const float*)d_in[7];
    const float* ln1_g       = (const float*)d_in[8];
    const float* ln1_b       = (const float*)d_in[9];
    const float* ln2_g       = (const float*)d_in[10];
    const float* ln2_b       = (const float*)d_in[11];
    const float* wq          = (const float*)d_in[12];
    const float* bq          = (const float*)d_in[13];
    const float* wk          = (const float*)d_in[14];
    const float* wv          = (const float*)d_in[16];
    const float* bv          = (const float*)d_in[17];
    const float* wp          = (const float*)d_in[18];
    const float* bp          = (const float*)d_in[19];
    const float* fw1         = (const float*)d_in[20];
    const float* fb1         = (const float*)d_in[21];
    const float* fw2         = (const float*)d_in[22];
    const float* fb2         = (const float*)d_in[23];
    float* out = (float*)d_out;

    upsample_kernel<<<1024, 256>>>(coords1, up_mask, fte_w1, fte_w2, wk, out);
    decoder_kernel<<<2048, 32>>>(cost_maps, cost_memory, coords1,
                                 fte_b1, fte_b2,
                                 ln1_g, ln1_b, ln2_g, ln2_b,
                                 wq, bq, wv, bv, wp, bp,
                                 fw1, fb1, fw2, fb2, out);
}

// round 8
// speedup vs baseline: 1.1880x; 1.1880x over previous
#include <cuda_runtime.h>
#include <math.h>

#define FLOW_SZ 1048576       // 2*2*512*512

// ---- device scratch (filled by upsample kernel's prep blocks) ----
__device__ __align__(16) float g_w1t[81 * 64];     // g_w1t[c*64+o] = fte_w1[o*81+c]
__device__ __align__(16) float g_w2t[64 * 64];     // g_w2t[c*64+o] = fte_w2[o*64+c]
__device__ __align__(16) float g_wk_t[64 * 128];   // g_wk_t[d*128+c] = wk[c*64+d]

__device__ __forceinline__ float gelu_exact(float x) {
    return 0.5f * x * (1.0f + erff(x * 0.70710678118654752f));
}

__device__ __forceinline__ float samp_map(const float* __restrict__ p, int ix, int iy) {
    if ((unsigned)ix < 64u && (unsigned)iy < 64u) return p[iy * 64 + ix];
    return 0.0f;
}

__device__ __forceinline__ float4 fma4(float s, float4 a, float4 b) {
    return make_float4(fmaf(s, a.x, b.x), fmaf(s, a.y, b.y),
                       fmaf(s, a.z, b.z), fmaf(s, a.w, b.w));
}

__device__ __forceinline__ float posenc(float cx, float cy, int o) {
    int r = o >> 4, f = o & 15;
    float base = (r < 2) ? cx : cy;
    float ang = 3.14f * base * (float)f / 200.0f;
    return ((r & 1) == 0) ? sinf(ang) : cosf(ang);
}

// Dual-token matmul: out[o] = sum_c act[t][c] * w[c*64+o], o0=2*lane, o1=2*lane+1.
template <int ROWS>
__device__ __forceinline__ void mm2(const float* a0, const float* a1,
                                    const float* __restrict__ w,
                                    int l, float2& r0, float2& r1)
{
    const float* wl = w + 2 * l;
    #pragma unroll 4
    for (int c = 0; c < ROWS; c += 4) {
        float4 x0 = *(const float4*)(a0 + c);
        float4 x1 = *(const float4*)(a1 + c);
        float2 wa = *(const float2*)(wl + (c + 0) * 64);
        float2 wb = *(const float2*)(wl + (c + 1) * 64);
        float2 wc = *(const float2*)(wl + (c + 2) * 64);
        float2 wd = *(const float2*)(wl + (c + 3) * 64);
        r0.x = fmaf(x0.x, wa.x, r0.x); r0.y = fmaf(x0.x, wa.y, r0.y);
        r1.x = fmaf(x1.x, wa.x, r1.x); r1.y = fmaf(x1.x, wa.y, r1.y);
        r0.x = fmaf(x0.y, wb.x, r0.x); r0.y = fmaf(x0.y, wb.y, r0.y);
        r1.x = fmaf(x1.y, wb.x, r1.x); r1.y = fmaf(x1.y, wb.y, r1.y);
        r0.x = fmaf(x0.z, wc.x, r0.x); r0.y = fmaf(x0.z, wc.y, r0.y);
        r1.x = fmaf(x1.z, wc.x, r1.x); r1.y = fmaf(x1.z, wc.y, r1.y);
        r0.x = fmaf(x0.w, wd.x, r0.x); r0.y = fmaf(x0.w, wd.y, r0.y);
        r1.x = fmaf(x1.w, wd.x, r1.x); r1.y = fmaf(x1.w, wd.y, r1.y);
    }
}

// Per-warp shared state for 2 tokens. cm rows padded to 132 floats
// (conflict-free row-indexed float4 access). No t/u buffer: scores are
// computed via register fragments + shuffle reduction, and u overwrites cm.
struct __align__(16) WarpSmem {
    float cm[2][1056];    // 8 x 132 cost_memory rows; overwritten by u[h][c]
    float corr[2][88];    // 81 correlation values
    float attn[2][64];    // softmaxed attention
    float qlin[2][64];
    float A[2][64];       // gelu(fte1) -> attn_out -> ffn hidden
    float B[2][64];       // normed (+enc) vectors
    float sh[2][64];      // short (residual)
    float xs[2][64];      // final
};

// Reduce v[8] (partial scores for j=0..7, each lane holding a partial over its
// 4-c slice) across all 32 lanes. Returns the full score for j=(l>>2)&7.
__device__ __forceinline__ float score_reduce(float* v, int l) {
    bool up = (l & 16) != 0;
    #pragma unroll
    for (int i = 0; i < 4; ++i) {
        float send = up ? v[i] : v[i + 4];
        float recv = __shfl_xor_sync(0xffffffffu, send, 16);
        v[i] = (up ? v[i + 4] : v[i]) + recv;
    }
    up = (l & 8) != 0;
    #pragma unroll
    for (int i = 0; i < 2; ++i) {
        float send = up ? v[i] : v[i + 2];
        float recv = __shfl_xor_sync(0xffffffffu, send, 8);
        v[i] = (up ? v[i + 2] : v[i]) + recv;
    }
    up = (l & 4) != 0;
    {
        float send = up ? v[0] : v[1];
        float recv = __shfl_xor_sync(0xffffffffu, send, 4);
        v[0] = (up ? v[1] : v[0]) + recv;
    }
    v[0] += __shfl_xor_sync(0xffffffffu, v[0], 2);
    v[0] += __shfl_xor_sync(0xffffffffu, v[0], 1);
    return v[0];
}

__device__ __forceinline__ float softmax_j(float s, int l) {
    float mx = s;
    mx = fmaxf(mx, __shfl_xor_sync(0xffffffffu, mx, 4));
    mx = fmaxf(mx, __shfl_xor_sync(0xffffffffu, mx, 8));
    mx = fmaxf(mx, __shfl_xor_sync(0xffffffffu, mx, 16));
    float e = __expf(s - mx);
    float sum = e;
    sum += __shfl_xor_sync(0xffffffffu, sum, 4);
    sum += __shfl_xor_sync(0xffffffffu, sum, 8);
    sum += __shfl_xor_sync(0xffffffffu, sum, 16);
    return e / sum;
}

__global__ __launch_bounds__(64) void decoder_kernel(
    const float* __restrict__ cost_maps,
    const float* __restrict__ cost_memory,
    const float* __restrict__ coords1,
    const float* __restrict__ fte_b1,
    const float* __restrict__ fte_b2,
    const float* __restrict__ ln1_g, const float* __restrict__ ln1_b,
    const float* __restrict__ ln2_g, const float* __restrict__ ln2_b,
    const float* __restrict__ wq,  const float* __restrict__ bq,
    const float* __restrict__ wv,  const float* __restrict__ bv,
    const float* __restrict__ wp,  const float* __restrict__ bp,
    const float* __restrict__ fw1, const float* __restrict__ fb1,
    const float* __restrict__ fw2, const float* __restrict__ fb2,
    float* __restrict__ out)
{
    __shared__ WarpSmem ts[2];
    const int warp = threadIdx.x >> 5;
    const int l = threadIdx.x & 31;
    const int n0 = blockIdx.x * 4 + warp * 2;   // tokens n0, n0+1
    WarpSmem& S = ts[warp];

    const int b = n0 >> 12;
    const int pix0 = n0 & 4095;
    const float cx0 = coords1[b * 8192 + pix0];
    const float cy0 = coords1[b * 8192 + 4096 + pix0];
    const float cx1 = coords1[b * 8192 + pix0 + 1];
    const float cy1 = coords1[b * 8192 + 4096 + pix0 + 1];
    const int o0 = 2 * l, o1 = 2 * l + 1;

    // ---- phase 0: load cost_memory rows into padded smem ----
    #pragma unroll
    for (int t = 0; t < 2; ++t) {
        const float4* src = (const float4*)(cost_memory + (size_t)(n0 + t) * 1024);
        #pragma unroll
        for (int r = 0; r < 8; ++r)
            ((float4*)&S.cm[t][r * 132])[l] = src[r * 32 + l];
    }

    // ---- phase 1: bilinear correlation sampling (81 per token) ----
    #pragma unroll
    for (int t = 0; t < 2; ++t) {
        const float* cmap = cost_maps + (size_t)(n0 + t) * 4096;
        const float cx = t ? cx1 : cx0;
        const float cy = t ? cy1 : cy0;
        for (int s = l; s < 81; s += 32) {
            int si = s / 9, sj = s - si * 9;
            float px = cx + (float)(si - 4);
            float py = cy + (float)(sj - 4);
            float fx0 = floorf(px), fy0 = floorf(py);
            float wx = px - fx0, wy = py - fy0;
            int ix = (int)fx0, iy = (int)fy0;
            float v00 = samp_map(cmap, ix,     iy);
            float v10 = samp_map(cmap, ix + 1, iy);
            float v01 = samp_map(cmap, ix,     iy + 1);
            float v11 = samp_map(cmap, ix + 1, iy + 1);
            S.corr[t][s] = v00 * (1.f - wx) * (1.f - wy) + v10 * wx * (1.f - wy)
                         + v01 * (1.f - wx) * wy         + v11 * wx * wy;
        }
    }
    __syncwarp();

    // ---- phase 2: FTE1 = gelu(corr @ W1 + b1) ----
    {
        float2 bb = *(const float2*)(fte_b1 + o0);
        float2 r0 = bb, r1 = bb;
        mm2<80>(S.corr[0], S.corr[1], g_w1t, l, r0, r1);
        float2 w80 = *(const float2*)(g_w1t + 80 * 64 + o0);
        float a80_0 = S.corr[0][80], a80_1 = S.corr[1][80];
        r0.x = fmaf(a80_0, w80.x, r0.x); r0.y = fmaf(a80_0, w80.y, r0.y);
        r1.x = fmaf(a80_1, w80.x, r1.x); r1.y = fmaf(a80_1, w80.y, r1.y);
        *(float2*)&S.A[0][o0] = make_float2(gelu_exact(r0.x), gelu_exact(r0.y));
        *(float2*)&S.A[1][o0] = make_float2(gelu_exact(r1.x), gelu_exact(r1.y));
    }
    __syncwarp();

    // ---- phase 3: query = A @ W2 + b2 (= short) ----
    float2 q0, q1;
    {
        float2 bb = *(const float2*)(fte_b2 + o0);
        q0 = bb; q1 = bb;
        mm2<64>(S.A[0], S.A[1], g_w2t, l, q0, q1);
        *(float2*)&S.sh[0][o0] = q0;
        *(float2*)&S.sh[1][o0] = q1;
    }

    // ---- phase 4: layernorm1 + positional encoding ----
    {
        float s0 = q0.x + q0.y, s1 = q1.x + q1.y;
        #pragma unroll
        for (int off = 16; off; off >>= 1) {
            s0 += __shfl_xor_sync(0xffffffffu, s0, off);
            s1 += __shfl_xor_sync(0xffffffffu, s1, off);
        }
        float m0 = s0 * (1.f / 64.f), m1 = s1 * (1.f / 64.f);
        float d00 = q0.x - m0, d01 = q0.y - m0;
        float d10 = q1.x - m1, d11 = q1.y - m1;
        float v0 = d00 * d00 + d01 * d01, v1 = d10 * d10 + d11 * d11;
        #pragma unroll
        for (int off = 16; off; off >>= 1) {
            v0 += __shfl_xor_sync(0xffffffffu, v0, off);
            v1 += __shfl_xor_sync(0xffffffffu, v1, off);
        }
        float i0 = rsqrtf(v0 * (1.f / 64.f) + 1e-5f);
        float i1 = rsqrtf(v1 * (1.f / 64.f) + 1e-5f);
        float2 g2 = *(const float2*)(ln1_g + o0);
        float2 b2v = *(const float2*)(ln1_b + o0);
        float e00 = posenc(cx0, cy0, o0), e01 = posenc(cx0, cy0, o1);
        float e10 = posenc(cx1, cy1, o0), e11 = posenc(cx1, cy1, o1);
        *(float2*)&S.B[0][o0] = make_float2(d00 * i0 * g2.x + b2v.x + e00,
                                            d01 * i0 * g2.y + b2v.y + e01);
        *(float2*)&S.B[1][o0] = make_float2(d10 * i1 * g2.x + b2v.x + e10,
                                            d11 * i1 * g2.y + b2v.y + e11);
    }
    __syncwarp();

    // ---- phase 5: qlin = B @ wq + bq ----
    {
        float2 bb = *(const float2*)(bq + o0);
        float2 r0 = bb, r1 = bb;
        mm2<64>(S.B[0], S.B[1], wq, l, r0, r1);
        *(float2*)&S.qlin[0][o0] = r0;
        *(float2*)&S.qlin[1][o0] = r1;
    }
    __syncwarp();

    // ---- phases 6-8 fused: scores (no t materialization) + softmax + u ----
    {
        // cm fragments: lane's 4-c slice of every row, both tokens
        float4 cmf0[8], cmf1[8];
        #pragma unroll
        for (int j = 0; j < 8; ++j) {
            cmf0[j] = *(const float4*)&S.cm[0][j * 132 + 4 * l];
            cmf1[j] = *(const float4*)&S.cm[1][j * 132 + 4 * l];
        }
        const float4* wk4 = (const float4*)g_wk_t;
        const float scale = 0.35355339059327373f;
        #pragma unroll
        for (int h = 0; h < 8; ++h) {
            float q0v[8], q1v[8];
            *(float4*)&q0v[0] = *(const float4*)&S.qlin[0][h * 8];
            *(float4*)&q0v[4] = *(const float4*)&S.qlin[0][h * 8 + 4];
            *(float4*)&q1v[0] = *(const float4*)&S.qlin[1][h * 8];
            *(float4*)&q1v[4] = *(const float4*)&S.qlin[1][h * 8 + 4];
            float4 tf0 = make_float4(0.f, 0.f, 0.f, 0.f), tf1 = tf0;
            #pragma unroll
            for (int e = 0; e < 8; ++e) {
                float4 w = wk4[(h * 8 + e) * 32 + l];
                tf0 = fma4(q0v[e], w, tf0);
                tf1 = fma4(q1v[e], w, tf1);
            }
            // token 0
            {
                float v[8];
                #pragma unroll
                for (int j = 0; j < 8; ++j)
                    v[j] = fmaf(tf0.x, cmf0[j].x, fmaf(tf0.y, cmf0[j].y,
                           fmaf(tf0.z, cmf0[j].z, tf0.w * cmf0[j].w)));
                float s = score_reduce(v, l) * scale;
                float a = softmax_j(s, l);
                if ((l & 3) == 0)
                    S.attn[0][h * 8 + ((l >> 2) & 7)] = a;
            }
            // token 1
            {
                float v[8];
                #pragma unroll
                for (int j = 0; j < 8; ++j)
                    v[j] = fmaf(tf1.x, cmf1[j].x, fmaf(tf1.y, cmf1[j].y,
                           fmaf(tf1.z, cmf1[j].z, tf1.w * cmf1[j].w)));
                float s = score_reduce(v, l) * scale;
                float a = softmax_j(s, l);
                if ((l & 3) == 0)
                    S.attn[1][h * 8 + ((l >> 2) & 7)] = a;
            }
        }
        __syncwarp();   // attn visible to all lanes

        // u[h] = sum_j attn[h][j] * cm[j]; overwrite cm rows (lane-local cols)
        {
            float4 ua[8];
            #pragma unroll
            for (int h = 0; h < 8; ++h) ua[h] = make_float4(0.f, 0.f, 0.f, 0.f);
            #pragma unroll
            for (int j = 0; j < 8; ++j) {
                float4 m = cmf0[j];
                #pragma unroll
                for (int h = 0; h < 8; ++h)
                    ua[h] = fma4(S.attn[0][h * 8 + j], m, ua[h]);
            }
            #pragma unroll
            for (int h = 0; h < 8; ++h)
                *(float4*)&S.cm[0][h * 132 + 4 * l] = ua[h];
        }
        {
            float4 ua[8];
            #pragma unroll
            for (int h = 0; h < 8; ++h) ua[h] = make_float4(0.f, 0.f, 0.f, 0.f);
            #pragma unroll
            for (int j = 0; j < 8; ++j) {
                float4 m = cmf1[j];
                #pragma unroll
                for (int h = 0; h < 8; ++h)
                    ua[h] = fma4(S.attn[1][h * 8 + j], m, ua[h]);
            }
            #pragma unroll
            for (int h = 0; h < 8; ++h)
                *(float4*)&S.cm[1][h * 132 + 4 * l] = ua[h];
        }
    }
    __syncwarp();

    // ---- phase 9: out = u @ wv + bv  (u lives in cm rows now) ----
    {
        float2 bb = *(const float2*)(bv + o0);
        float2 r0 = bb, r1 = bb;
        const int h = l >> 2;   // head of both o0 and o1
        mm2<128>(&S.cm[0][h * 132], &S.cm[1][h * 132], wv, l, r0, r1);
        *(float2*)&S.A[0][o0] = r0;
        *(float2*)&S.A[1][o0] = r1;
    }
    __syncwarp();

    // ---- phase 10: x = concat(out, short) @ wp + bp + short ----
    float2 x0, x1;
    {
        float2 bb = *(const float2*)(bp + o0);
        x0 = bb; x1 = bb;
        mm2<64>(S.A[0], S.A[1], wp, l, x0, x1);
        mm2<64>(S.sh[0], S.sh[1], wp + 64 * 64, l, x0, x1);
        float2 sh0 = *(const float2*)&S.sh[0][o0];
        float2 sh1 = *(const float2*)&S.sh[1][o0];
        x0.x += sh0.x; x0.y += sh0.y;
        x1.x += sh1.x; x1.y += sh1.y;
    }

    // ---- phase 11: layernorm2 ----
    {
        float s0 = x0.x + x0.y, s1 = x1.x + x1.y;
        #pragma unroll
        for (int off = 16; off; off >>= 1) {
            s0 += __shfl_xor_sync(0xffffffffu, s0, off);
            s1 += __shfl_xor_sync(0xffffffffu, s1, off);
        }
        float m0 = s0 * (1.f / 64.f), m1 = s1 * (1.f / 64.f);
        float d00 = x0.x - m0, d01 = x0.y - m0;
        float d10 = x1.x - m1, d11 = x1.y - m1;
        float v0 = d00 * d00 + d01 * d01, v1 = d10 * d10 + d11 * d11;
        #pragma unroll
        for (int off = 16; off; off >>= 1) {
            v0 += __shfl_xor_sync(0xffffffffu, v0, off);
            v1 += __shfl_xor_sync(0xffffffffu, v1, off);
        }
        float i0 = rsqrtf(v0 * (1.f / 64.f) + 1e-5f);
        float i1 = rsqrtf(v1 * (1.f / 64.f) + 1e-5f);
        float2 g2 = *(const float2*)(ln2_g + o0);
        float2 b2v = *(const float2*)(ln2_b + o0);
        *(float2*)&S.B[0][o0] = make_float2(d00 * i0 * g2.x + b2v.x,
                                            d01 * i0 * g2.y + b2v.y);
        *(float2*)&S.B[1][o0] = make_float2(d10 * i1 * g2.x + b2v.x,
                                            d11 * i1 * g2.y + b2v.y);
    }
    __syncwarp();

    // ---- phase 12: FFN hidden ----
    {
        float2 bb = *(const float2*)(fb1 + o0);
        float2 r0 = bb, r1 = bb;
        mm2<64>(S.B[0], S.B[1], fw1, l, r0, r1);
        *(float2*)&S.A[0][o0] = make_float2(gelu_exact(r0.x), gelu_exact(r0.y));
        *(float2*)&S.A[1][o0] = make_float2(gelu_exact(r1.x), gelu_exact(r1.y));
    }
    __syncwarp();

    // ---- phase 13: FFN out + residual ----
    {
        float2 bb = *(const float2*)(fb2 + o0);
        float2 r0 = bb, r1 = bb;
        mm2<64>(S.A[0], S.A[1], fw2, l, r0, r1);
        *(float2*)&S.xs[0][o0] = make_float2(x0.x + r0.x, x0.y + r0.y);
        *(float2*)&S.xs[1][o0] = make_float2(x1.x + r1.x, x1.y + r1.y);
    }

    // ---- phase 14: block-staged transposed writeout (STG.128) ----
    __syncthreads();
    {
        int nb = blockIdx.x * 4;
        int bb = nb >> 12;
        int px = nb & 4095;
        float* cg = out + FLOW_SZ + (size_t)bb * 64 * 4096 + px;
        int o = threadIdx.x;   // 0..63
        float4 v = make_float4(ts[0].xs[0][o], ts[0].xs[1][o],
                               ts[1].xs[0][o], ts[1].xs[1][o]);
        *(float4*)(cg + (size_t)o * 4096) = v;
    }
}

// ============================================================================
// Convex upsampling; blocks 0..23 transpose FTE weights, blocks 24..55
// transpose wk for the decoder's fused score phase.
// ============================================================================
__global__ __launch_bounds__(256) void upsample_kernel(
    const float* __restrict__ coords1,
    const float* __restrict__ up_mask,
    const float* __restrict__ fte_w1,
    const float* __restrict__ fte_w2,
    const float* __restrict__ wk,
    float* __restrict__ out)
{
    __shared__ float slab[576 * 8];
    __shared__ float fl[2][3][10];
    __shared__ float outp[2 * 8 * 64];

    int blk = blockIdx.x;
    int tid = threadIdx.x;

    if (blk < 24) {
        int i = blk * 256 + tid;
        if (i < 81 * 64) {
            int c = i >> 6, o = i & 63;
            g_w1t[i] = fte_w1[o * 81 + c];
        }
        if (i < 64 * 64) {
            int c = i >> 6, o = i & 63;
            g_w2t[i] = fte_w2[o * 64 + c];
        }
    } else if (blk < 56) {
        int i = (blk - 24) * 256 + tid;   // [0, 8192)
        int d = i >> 7, c = i & 127;
        g_wk_t[i] = wk[c * 64 + d];
    }

    int b   = blk >> 9;
    int rem = blk & 511;
    int y   = rem >> 3;
    int x0  = (rem & 7) << 3;

    const float* mbase = up_mask + (size_t)b * 576 * 4096 + y * 64 + x0;
    for (int idx = tid; idx < 1152; idx += 256) {
        int ch = idx >> 1, half = idx & 1;
        ((float4*)slab)[idx] =
            *(const float4*)(mbase + (size_t)ch * 4096 + half * 4);
    }
    if (tid < 60) {
        int c = tid / 30, r2 = tid % 30, r = r2 / 10, cc = r2 % 10;
        int yy = y + r - 1, xx = x0 + cc - 1;
        float v = 0.0f;
        if ((unsigned)yy < 64u && (unsigned)xx < 64u) {
            float coord = coords1[b * 8192 + c * 4096 + yy * 64 + xx];
            v = 8.0f * (coord - (float)(c == 0 ? xx : yy));
        }
        fl[c][r][cc] = v;
    }
    __syncthreads();

    for (int q = tid; q < 512; q += 256) {
        int p  = q & 7;
        int ij = q >> 3;
        int i  = ij >> 3, j = ij & 7;
        float w[9];
        float mx = -1e30f;
        #pragma unroll
        for (int kk = 0; kk < 9; ++kk) {
            w[kk] = slab[(kk * 64 + ij) * 8 + p];
            mx = fmaxf(mx, w[kk]);
        }
        float s = 0.f;
        #pragma unroll
        for (int kk = 0; kk < 9; ++kk) { w[kk] = __expf(w[kk] - mx); s += w[kk]; }
        float inv = 1.0f / s;
        float u0 = 0.f, u1 = 0.f;
        #pragma unroll
        for (int kk = 0; kk < 9; ++kk) {
            int dy = kk / 3, dx = kk - dy * 3;
            u0 = fmaf(w[kk], fl[0][dy][p + dx], u0);
            u1 = fmaf(w[kk], fl[1][dy][p + dx], u1);
        }
        int col = p * 8 + j;
        outp[(0 * 8 + i) * 64 + col] = u0 * inv;
        outp[(1 * 8 + i) * 64 + col] = u1 * inv;
    }
    __syncthreads();

    float* obase = out + (size_t)b * 2 * 512 * 512 + (size_t)(8 * y) * 512 + 8 * x0;
    for (int idx = tid; idx < 1024; idx += 256) {
        int c = idx >> 9, rest = idx & 511;
        int i = rest >> 6, col = rest & 63;
        obase[(size_t)c * 512 * 512 + i * 512 + col] = outp[(c * 8 + i) * 64 + col];
    }
}

extern "C" void kernel_launch(void* const* d_in, const int* in_sizes, int n_in,
                              void* d_out, int out_size) {
    const float* cost_maps   = (const float*)d_in[0];
    const float* cost_memory = (const float*)d_in[1];
    const float* coords1     = (const float*)d_in[2];
    const float* up_mask     = (const float*)d_in[3];
    const float* fte_w1      = (const float*)d_in[4];
    const float* fte_b1      = (const float*)d_in[5];
    const float* fte_w2      = (const float*)d_in[6];
    const float* fte_b2      = (const float*)d_in[7];
    const float* ln1_g       = (const float*)d_in[8];
    const float* ln1_b       = (const float*)d_in[9];
    const float* ln2_g       = (const float*)d_in[10];
    const float* ln2_b       = (const float*)d_in[11];
    const float* wq          = (const float*)d_in[12];
    const float* bq          = (const float*)d_in[13];
    const float* wk          = (const float*)d_in[14];
    const float* wv          = (const float*)d_in[16];
    const float* bv          = (const float*)d_in[17];
    const float* wp          = (const float*)d_in[18];
    const float* bp          = (const float*)d_in[19];
    const float* fw1         = (const float*)d_in[20];
    const float* fb1         = (const float*)d_in[21];
    const float* fw2         = (const float*)d_in[22];
    const float* fb2         = (const float*)d_in[23];
    float* out = (float*)d_out;

    upsample_kernel<<<1024, 256>>>(coords1, up_mask, fte_w1, fte_w2, wk, out);
    decoder_kernel<<<2048, 64>>>(cost_maps, cost_memory, coords1,
                                 fte_b1, fte_b2,
                                 ln1_g, ln1_b, ln2_g, ln2_b,
                                 wq, bq, wv, bv, wp, bp,
                                 fw1, fb1, fw2, fb2, out);
}

// round 9
// speedup vs baseline: 1.2208x; 1.0276x over previous
#include <cuda_runtime.h>
#include <math.h>

#define FLOW_SZ 1048576       // 2*2*512*512

// ---- device scratch (filled by upsample kernel's prep blocks) ----
__device__ __align__(16) float g_w1t[81 * 64];     // g_w1t[c*64+o] = fte_w1[o*81+c]
__device__ __align__(16) float g_w2t[64 * 64];     // g_w2t[c*64+o] = fte_w2[o*64+c]
__device__ __align__(16) float g_wk_t[64 * 128];   // g_wk_t[d*128+c] = wk[c*64+d]

__device__ __forceinline__ float gelu_exact(float x) {
    return 0.5f * x * (1.0f + erff(x * 0.70710678118654752f));
}

__device__ __forceinline__ float samp_map(const float* __restrict__ p, int ix, int iy) {
    if ((unsigned)ix < 64u && (unsigned)iy < 64u) return p[iy * 64 + ix];
    return 0.0f;
}

__device__ __forceinline__ float4 fma4(float s, float4 a, float4 b) {
    return make_float4(fmaf(s, a.x, b.x), fmaf(s, a.y, b.y),
                       fmaf(s, a.z, b.z), fmaf(s, a.w, b.w));
}

__device__ __forceinline__ float posenc(float cx, float cy, int o) {
    int r = o >> 4, f = o & 15;
    float base = (r < 2) ? cx : cy;
    float ang = 3.14f * base * (float)f / 200.0f;
    return ((r & 1) == 0) ? __sinf(ang) : __cosf(ang);
}

// Dual-token matmul: out[o] = sum_c act[t][c] * w[c*64+o], o0=2*lane, o1=2*lane+1.
template <int ROWS>
__device__ __forceinline__ void mm2(const float* a0, const float* a1,
                                    const float* __restrict__ w,
                                    int l, float2& r0, float2& r1)
{
    const float* wl = w + 2 * l;
    #pragma unroll 4
    for (int c = 0; c < ROWS; c += 4) {
        float4 x0 = *(const float4*)(a0 + c);
        float4 x1 = *(const float4*)(a1 + c);
        float2 wa = *(const float2*)(wl + (c + 0) * 64);
        float2 wb = *(const float2*)(wl + (c + 1) * 64);
        float2 wc = *(const float2*)(wl + (c + 2) * 64);
        float2 wd = *(const float2*)(wl + (c + 3) * 64);
        r0.x = fmaf(x0.x, wa.x, r0.x); r0.y = fmaf(x0.x, wa.y, r0.y);
        r1.x = fmaf(x1.x, wa.x, r1.x); r1.y = fmaf(x1.x, wa.y, r1.y);
        r0.x = fmaf(x0.y, wb.x, r0.x); r0.y = fmaf(x0.y, wb.y, r0.y);
        r1.x = fmaf(x1.y, wb.x, r1.x); r1.y = fmaf(x1.y, wb.y, r1.y);
        r0.x = fmaf(x0.z, wc.x, r0.x); r0.y = fmaf(x0.z, wc.y, r0.y);
        r1.x = fmaf(x1.z, wc.x, r1.x); r1.y = fmaf(x1.z, wc.y, r1.y);
        r0.x = fmaf(x0.w, wd.x, r0.x); r0.y = fmaf(x0.w, wd.y, r0.y);
        r1.x = fmaf(x1.w, wd.x, r1.x); r1.y = fmaf(x1.w, wd.y, r1.y);
    }
}

// Per-warp shared state for 2 tokens. cm rows padded to 132 floats
// (conflict-free row-indexed float4 access). No t/u buffer: scores are
// computed via register fragments + shuffle reduction, and u overwrites cm.
struct __align__(16) WarpSmem {
    float cm[2][1056];    // 8 x 132 cost_memory rows; overwritten by u[h][c]
    float corr[2][88];    // 81 correlation values
    float attn[2][64];    // softmaxed attention
    float qlin[2][64];
    float A[2][64];       // gelu(fte1) -> attn_out -> ffn hidden
    float B[2][64];       // normed (+enc) vectors
    float sh[2][64];      // short (residual)
    float xs[2][64];      // final
};

// Reduce v[8] (partial scores for j=0..7, each lane holding a partial over its
// 4-c slice) across all 32 lanes. Returns the full score for j=(l>>2)&7.
__device__ __forceinline__ float score_reduce(float* v, int l) {
    bool up = (l & 16) != 0;
    #pragma unroll
    for (int i = 0; i < 4; ++i) {
        float send = up ? v[i] : v[i + 4];
        float recv = __shfl_xor_sync(0xffffffffu, send, 16);
        v[i] = (up ? v[i + 4] : v[i]) + recv;
    }
    up = (l & 8) != 0;
    #pragma unroll
    for (int i = 0; i < 2; ++i) {
        float send = up ? v[i] : v[i + 2];
        float recv = __shfl_xor_sync(0xffffffffu, send, 8);
        v[i] = (up ? v[i + 2] : v[i]) + recv;
    }
    up = (l & 4) != 0;
    {
        float send = up ? v[0] : v[1];
        float recv = __shfl_xor_sync(0xffffffffu, send, 4);
        v[0] = (up ? v[1] : v[0]) + recv;
    }
    v[0] += __shfl_xor_sync(0xffffffffu, v[0], 2);
    v[0] += __shfl_xor_sync(0xffffffffu, v[0], 1);
    return v[0];
}

__device__ __forceinline__ float softmax_j(float s, int l) {
    float mx = s;
    mx = fmaxf(mx, __shfl_xor_sync(0xffffffffu, mx, 4));
    mx = fmaxf(mx, __shfl_xor_sync(0xffffffffu, mx, 8));
    mx = fmaxf(mx, __shfl_xor_sync(0xffffffffu, mx, 16));
    float e = __expf(s - mx);
    float sum = e;
    sum += __shfl_xor_sync(0xffffffffu, sum, 4);
    sum += __shfl_xor_sync(0xffffffffu, sum, 8);
    sum += __shfl_xor_sync(0xffffffffu, sum, 16);
    return e / sum;
}

__global__ __launch_bounds__(64) void decoder_kernel(
    const float* __restrict__ cost_maps,
    const float* __restrict__ cost_memory,
    const float* __restrict__ coords1,
    const float* __restrict__ fte_b1,
    const float* __restrict__ fte_b2,
    const float* __restrict__ ln1_g, const float* __restrict__ ln1_b,
    const float* __restrict__ ln2_g, const float* __restrict__ ln2_b,
    const float* __restrict__ wq,  const float* __restrict__ bq,
    const float* __restrict__ wv,  const float* __restrict__ bv,
    const float* __restrict__ wp,  const float* __restrict__ bp,
    const float* __restrict__ fw1, const float* __restrict__ fb1,
    const float* __restrict__ fw2, const float* __restrict__ fb2,
    float* __restrict__ out)
{
    __shared__ WarpSmem ts[2];
    const int warp = threadIdx.x >> 5;
    const int l = threadIdx.x & 31;
    const int n0 = blockIdx.x * 4 + warp * 2;   // tokens n0, n0+1
    WarpSmem& S = ts[warp];

    const int b = n0 >> 12;
    const int pix0 = n0 & 4095;
    const float cx0 = coords1[b * 8192 + pix0];
    const float cy0 = coords1[b * 8192 + 4096 + pix0];
    const float cx1 = coords1[b * 8192 + pix0 + 1];
    const float cy1 = coords1[b * 8192 + 4096 + pix0 + 1];
    const int o0 = 2 * l, o1 = 2 * l + 1;

    // ---- phase 0: load cost_memory rows into padded smem ----
    #pragma unroll
    for (int t = 0; t < 2; ++t) {
        const float4* src = (const float4*)(cost_memory + (size_t)(n0 + t) * 1024);
        #pragma unroll
        for (int r = 0; r < 8; ++r)
            ((float4*)&S.cm[t][r * 132])[l] = src[r * 32 + l];
    }

    // ---- phase 1: bilinear correlation sampling (81 per token) ----
    // Lane mapping: si (x-offset) varies fastest across lanes so the four
    // gathers are row-contiguous (~2 cache lines per 9-lane group instead of 9).
    #pragma unroll
    for (int t = 0; t < 2; ++t) {
        const float* cmap = cost_maps + (size_t)(n0 + t) * 4096;
        const float cx = t ? cx1 : cx0;
        const float cy = t ? cy1 : cy0;
        for (int ss = l; ss < 81; ss += 32) {
            int si = ss % 9, sj = ss / 9;          // si fast across lanes
            float px = cx + (float)(si - 4);
            float py = cy + (float)(sj - 4);
            float fx0 = floorf(px), fy0 = floorf(py);
            float wx = px - fx0, wy = py - fy0;
            int ix = (int)fx0, iy = (int)fy0;
            float v00 = samp_map(cmap, ix,     iy);
            float v10 = samp_map(cmap, ix + 1, iy);
            float v01 = samp_map(cmap, ix,     iy + 1);
            float v11 = samp_map(cmap, ix + 1, iy + 1);
            S.corr[t][si * 9 + sj] =
                  v00 * (1.f - wx) * (1.f - wy) + v10 * wx * (1.f - wy)
                + v01 * (1.f - wx) * wy         + v11 * wx * wy;
        }
    }
    __syncwarp();

    // ---- phase 2: FTE1 = gelu(corr @ W1 + b1) ----
    {
        float2 bb = *(const float2*)(fte_b1 + o0);
        float2 r0 = bb, r1 = bb;
        mm2<80>(S.corr[0], S.corr[1], g_w1t, l, r0, r1);
        float2 w80 = *(const float2*)(g_w1t + 80 * 64 + o0);
        float a80_0 = S.corr[0][80], a80_1 = S.corr[1][80];
        r0.x = fmaf(a80_0, w80.x, r0.x); r0.y = fmaf(a80_0, w80.y, r0.y);
        r1.x = fmaf(a80_1, w80.x, r1.x); r1.y = fmaf(a80_1, w80.y, r1.y);
        *(float2*)&S.A[0][o0] = make_float2(gelu_exact(r0.x), gelu_exact(r0.y));
        *(float2*)&S.A[1][o0] = make_float2(gelu_exact(r1.x), gelu_exact(r1.y));
    }
    __syncwarp();

    // ---- phase 3: query = A @ W2 + b2 (= short) ----
    float2 q0, q1;
    {
        float2 bb = *(const float2*)(fte_b2 + o0);
        q0 = bb; q1 = bb;
        mm2<64>(S.A[0], S.A[1], g_w2t, l, q0, q1);
        *(float2*)&S.sh[0][o0] = q0;
        *(float2*)&S.sh[1][o0] = q1;
    }

    // ---- phase 4: layernorm1 + positional encoding ----
    {
        float s0 = q0.x + q0.y, s1 = q1.x + q1.y;
        #pragma unroll
        for (int off = 16; off; off >>= 1) {
            s0 += __shfl_xor_sync(0xffffffffu, s0, off);
            s1 += __shfl_xor_sync(0xffffffffu, s1, off);
        }
        float m0 = s0 * (1.f / 64.f), m1 = s1 * (1.f / 64.f);
        float d00 = q0.x - m0, d01 = q0.y - m0;
        float d10 = q1.x - m1, d11 = q1.y - m1;
        float v0 = d00 * d00 + d01 * d01, v1 = d10 * d10 + d11 * d11;
        #pragma unroll
        for (int off = 16; off; off >>= 1) {
            v0 += __shfl_xor_sync(0xffffffffu, v0, off);
            v1 += __shfl_xor_sync(0xffffffffu, v1, off);
        }
        float i0 = rsqrtf(v0 * (1.f / 64.f) + 1e-5f);
        float i1 = rsqrtf(v1 * (1.f / 64.f) + 1e-5f);
        float2 g2 = *(const float2*)(ln1_g + o0);
        float2 b2v = *(const float2*)(ln1_b + o0);
        float e00 = posenc(cx0, cy0, o0), e01 = posenc(cx0, cy0, o1);
        float e10 = posenc(cx1, cy1, o0), e11 = posenc(cx1, cy1, o1);
        *(float2*)&S.B[0][o0] = make_float2(d00 * i0 * g2.x + b2v.x + e00,
                                            d01 * i0 * g2.y + b2v.y + e01);
        *(float2*)&S.B[1][o0] = make_float2(d10 * i1 * g2.x + b2v.x + e10,
                                            d11 * i1 * g2.y + b2v.y + e11);
    }
    __syncwarp();

    // ---- phase 5: qlin = B @ wq + bq ----
    {
        float2 bb = *(const float2*)(bq + o0);
        float2 r0 = bb, r1 = bb;
        mm2<64>(S.B[0], S.B[1], wq, l, r0, r1);
        *(float2*)&S.qlin[0][o0] = r0;
        *(float2*)&S.qlin[1][o0] = r1;
    }
    __syncwarp();

    // ---- phases 6-8 fused: scores (no t materialization) + softmax + u ----
    {
        // cm fragments: lane's 4-c slice of every row, both tokens
        float4 cmf0[8], cmf1[8];
        #pragma unroll
        for (int j = 0; j < 8; ++j) {
            cmf0[j] = *(const float4*)&S.cm[0][j * 132 + 4 * l];
            cmf1[j] = *(const float4*)&S.cm[1][j * 132 + 4 * l];
        }
        const float4* wk4 = (const float4*)g_wk_t;
        const float scale = 0.35355339059327373f;
        #pragma unroll
        for (int h = 0; h < 8; ++h) {
            float q0v[8], q1v[8];
            *(float4*)&q0v[0] = *(const float4*)&S.qlin[0][h * 8];
            *(float4*)&q0v[4] = *(const float4*)&S.qlin[0][h * 8 + 4];
            *(float4*)&q1v[0] = *(const float4*)&S.qlin[1][h * 8];
            *(float4*)&q1v[4] = *(const float4*)&S.qlin[1][h * 8 + 4];
            float4 tf0 = make_float4(0.f, 0.f, 0.f, 0.f), tf1 = tf0;
            #pragma unroll
            for (int e = 0; e < 8; ++e) {
                float4 w = wk4[(h * 8 + e) * 32 + l];
                tf0 = fma4(q0v[e], w, tf0);
                tf1 = fma4(q1v[e], w, tf1);
            }
            // token 0
            {
                float v[8];
                #pragma unroll
                for (int j = 0; j < 8; ++j)
                    v[j] = fmaf(tf0.x, cmf0[j].x, fmaf(tf0.y, cmf0[j].y,
                           fmaf(tf0.z, cmf0[j].z, tf0.w * cmf0[j].w)));
                float s = score_reduce(v, l) * scale;
                float a = softmax_j(s, l);
                if ((l & 3) == 0)
                    S.attn[0][h * 8 + ((l >> 2) & 7)] = a;
            }
            // token 1
            {
                float v[8];
                #pragma unroll
                for (int j = 0; j < 8; ++j)
                    v[j] = fmaf(tf1.x, cmf1[j].x, fmaf(tf1.y, cmf1[j].y,
                           fmaf(tf1.z, cmf1[j].z, tf1.w * cmf1[j].w)));
                float s = score_reduce(v, l) * scale;
                float a = softmax_j(s, l);
                if ((l & 3) == 0)
                    S.attn[1][h * 8 + ((l >> 2) & 7)] = a;
            }
        }
        __syncwarp();   // attn visible to all lanes

        // u[h] = sum_j attn[h][j] * cm[j]; overwrite cm rows (lane-local cols)
        {
            float4 ua[8];
            #pragma unroll
            for (int h = 0; h < 8; ++h) ua[h] = make_float4(0.f, 0.f, 0.f, 0.f);
            #pragma unroll
            for (int j = 0; j < 8; ++j) {
                float4 m = cmf0[j];
                #pragma unroll
                for (int h = 0; h < 8; ++h)
                    ua[h] = fma4(S.attn[0][h * 8 + j], m, ua[h]);
            }
            #pragma unroll
            for (int h = 0; h < 8; ++h)
                *(float4*)&S.cm[0][h * 132 + 4 * l] = ua[h];
        }
        {
            float4 ua[8];
            #pragma unroll
            for (int h = 0; h < 8; ++h) ua[h] = make_float4(0.f, 0.f, 0.f, 0.f);
            #pragma unroll
            for (int j = 0; j < 8; ++j) {
                float4 m = cmf1[j];
                #pragma unroll
                for (int h = 0; h < 8; ++h)
                    ua[h] = fma4(S.attn[1][h * 8 + j], m, ua[h]);
            }
            #pragma unroll
            for (int h = 0; h < 8; ++h)
                *(float4*)&S.cm[1][h * 132 + 4 * l] = ua[h];
        }
    }
    __syncwarp();

    // ---- phase 9: out = u @ wv + bv  (u lives in cm rows now) ----
    {
        float2 bb = *(const float2*)(bv + o0);
        float2 r0 = bb, r1 = bb;
        const int h = l >> 2;   // head of both o0 and o1
        mm2<128>(&S.cm[0][h * 132], &S.cm[1][h * 132], wv, l, r0, r1);
        *(float2*)&S.A[0][o0] = r0;
        *(float2*)&S.A[1][o0] = r1;
    }
    __syncwarp();

    // ---- phase 10: x = concat(out, short) @ wp + bp + short ----
    float2 x0, x1;
    {
        float2 bb = *(const float2*)(bp + o0);
        x0 = bb; x1 = bb;
        mm2<64>(S.A[0], S.A[1], wp, l, x0, x1);
        mm2<64>(S.sh[0], S.sh[1], wp + 64 * 64, l, x0, x1);
        float2 sh0 = *(const float2*)&S.sh[0][o0];
        float2 sh1 = *(const float2*)&S.sh[1][o0];
        x0.x += sh0.x; x0.y += sh0.y;
        x1.x += sh1.x; x1.y += sh1.y;
    }

    // ---- phase 11: layernorm2 ----
    {
        float s0 = x0.x + x0.y, s1 = x1.x + x1.y;
        #pragma unroll
        for (int off = 16; off; off >>= 1) {
            s0 += __shfl_xor_sync(0xffffffffu, s0, off);
            s1 += __shfl_xor_sync(0xffffffffu, s1, off);
        }
        float m0 = s0 * (1.f / 64.f), m1 = s1 * (1.f / 64.f);
        float d00 = x0.x - m0, d01 = x0.y - m0;
        float d10 = x1.x - m1, d11 = x1.y - m1;
        float v0 = d00 * d00 + d01 * d01, v1 = d10 * d10 + d11 * d11;
        #pragma unroll
        for (int off = 16; off; off >>= 1) {
            v0 += __shfl_xor_sync(0xffffffffu, v0, off);
            v1 += __shfl_xor_sync(0xffffffffu, v1, off);
        }
        float i0 = rsqrtf(v0 * (1.f / 64.f) + 1e-5f);
        float i1 = rsqrtf(v1 * (1.f / 64.f) + 1e-5f);
        float2 g2 = *(const float2*)(ln2_g + o0);
        float2 b2v = *(const float2*)(ln2_b + o0);
        *(float2*)&S.B[0][o0] = make_float2(d00 * i0 * g2.x + b2v.x,
                                            d01 * i0 * g2.y + b2v.y);
        *(float2*)&S.B[1][o0] = make_float2(d10 * i1 * g2.x + b2v.x,
                                            d11 * i1 * g2.y + b2v.y);
    }
    __syncwarp();

    // ---- phase 12: FFN hidden ----
    {
        float2 bb = *(const float2*)(fb1 + o0);
        float2 r0 = bb, r1 = bb;
        mm2<64>(S.B[0], S.B[1], fw1, l, r0, r1);
        *(float2*)&S.A[0][o0] = make_float2(gelu_exact(r0.x), gelu_exact(r0.y));
        *(float2*)&S.A[1][o0] = make_float2(gelu_exact(r1.x), gelu_exact(r1.y));
    }
    __syncwarp();

    // ---- phase 13: FFN out + residual ----
    {
        float2 bb = *(const float2*)(fb2 + o0);
        float2 r0 = bb, r1 = bb;
        mm2<64>(S.A[0], S.A[1], fw2, l, r0, r1);
        *(float2*)&S.xs[0][o0] = make_float2(x0.x + r0.x, x0.y + r0.y);
        *(float2*)&S.xs[1][o0] = make_float2(x1.x + r1.x, x1.y + r1.y);
    }

    // ---- phase 14: block-staged transposed writeout (STG.128) ----
    __syncthreads();
    {
        int nb = blockIdx.x * 4;
        int bb = nb >> 12;
        int px = nb & 4095;
        float* cg = out + FLOW_SZ + (size_t)bb * 64 * 4096 + px;
        int o = threadIdx.x;   // 0..63
        float4 v = make_float4(ts[0].xs[0][o], ts[0].xs[1][o],
                               ts[1].xs[0][o], ts[1].xs[1][o]);
        *(float4*)(cg + (size_t)o * 4096) = v;
    }
}

// ============================================================================
// Convex upsampling; blocks 0..23 transpose FTE weights, blocks 24..55
// transpose wk for the decoder's fused score phase.
// ============================================================================
__global__ __launch_bounds__(256) void upsample_kernel(
    const float* __restrict__ coords1,
    const float* __restrict__ up_mask,
    const float* __restrict__ fte_w1,
    const float* __restrict__ fte_w2,
    const float* __restrict__ wk,
    float* __restrict__ out)
{
    __shared__ float slab[576 * 8];
    __shared__ float fl[2][3][10];
    __shared__ float outp[2 * 8 * 64];

    int blk = blockIdx.x;
    int tid = threadIdx.x;

    if (blk < 24) {
        int i = blk * 256 + tid;
        if (i < 81 * 64) {
            int c = i >> 6, o = i & 63;
            g_w1t[i] = fte_w1[o * 81 + c];
        }
        if (i < 64 * 64) {
            int c = i >> 6, o = i & 63;
            g_w2t[i] = fte_w2[o * 64 + c];
        }
    } else if (blk < 56) {
        int i = (blk - 24) * 256 + tid;   // [0, 8192)
        int d = i >> 7, c = i & 127;
        g_wk_t[i] = wk[c * 64 + d];
    }

    int b   = blk >> 9;
    int rem = blk & 511;
    int y   = rem >> 3;
    int x0  = (rem & 7) << 3;

    const float* mbase = up_mask + (size_t)b * 576 * 4096 + y * 64 + x0;
    for (int idx = tid; idx < 1152; idx += 256) {
        int ch = idx >> 1, half = idx & 1;
        ((float4*)slab)[idx] =
            *(const float4*)(mbase + (size_t)ch * 4096 + half * 4);
    }
    if (tid < 60) {
        int c = tid / 30, r2 = tid % 30, r = r2 / 10, cc = r2 % 10;
        int yy = y + r - 1, xx = x0 + cc - 1;
        float v = 0.0f;
        if ((unsigned)yy < 64u && (unsigned)xx < 64u) {
            float coord = coords1[b * 8192 + c * 4096 + yy * 64 + xx];
            v = 8.0f * (coord - (float)(c == 0 ? xx : yy));
        }
        fl[c][r][cc] = v;
    }
    __syncthreads();

    for (int q = tid; q < 512; q += 256) {
        int p  = q & 7;
        int ij = q >> 3;
        int i  = ij >> 3, j = ij & 7;
        float w[9];
        float mx = -1e30f;
        #pragma unroll
        for (int kk = 0; kk < 9; ++kk) {
            w[kk] = slab[(kk * 64 + ij) * 8 + p];
            mx = fmaxf(mx, w[kk]);
        }
        float s = 0.f;
        #pragma unroll
        for (int kk = 0; kk < 9; ++kk) { w[kk] = __expf(w[kk] - mx); s += w[kk]; }
        float inv = 1.0f / s;
        float u0 = 0.f, u1 = 0.f;
        #pragma unroll
        for (int kk = 0; kk < 9; ++kk) {
            int dy = kk / 3, dx = kk - dy * 3;
            u0 = fmaf(w[kk], fl[0][dy][p + dx], u0);
            u1 = fmaf(w[kk], fl[1][dy][p + dx], u1);
        }
        int col = p * 8 + j;
        outp[(0 * 8 + i) * 64 + col] = u0 * inv;
        outp[(1 * 8 + i) * 64 + col] = u1 * inv;
    }
    __syncthreads();

    float* obase = out + (size_t)b * 2 * 512 * 512 + (size_t)(8 * y) * 512 + 8 * x0;
    for (int idx = tid; idx < 1024; idx += 256) {
        int c = idx >> 9, rest = idx & 511;
        int i = rest >> 6, col = rest & 63;
        obase[(size_t)c * 512 * 512 + i * 512 + col] = outp[(c * 8 + i) * 64 + col];
    }
}

extern "C" void kernel_launch(void* const* d_in, const int* in_sizes, int n_in,
                              void* d_out, int out_size) {
    const float* cost_maps   = (const float*)d_in[0];
    const float* cost_memory = (const float*)d_in[1];
    const float* coords1     = (const float*)d_in[2];
    const float* up_mask     = (const float*)d_in[3];
    const float* fte_w1      = (const float*)d_in[4];
    const float* fte_b1      = (const float*)d_in[5];
    const float* fte_w2      = (const float*)d_in[6];
    const float* fte_b2      = (const float*)d_in[7];
    const float* ln1_g       = (const float*)d_in[8];
    const float* ln1_b       = (const float*)d_in[9];
    const float* ln2_g       = (const float*)d_in[10];
    const float* ln2_b       = (const float*)d_in[11];
    const float* wq          = (const float*)d_in[12];
    const float* bq          = (const float*)d_in[13];
    const float* wk          = (const float*)d_in[14];
    const float* wv          = (const float*)d_in[16];
    const float* bv          = (const float*)d_in[17];
    const float* wp          = (const float*)d_in[18];
    const float* bp          = (const float*)d_in[19];
    const float* fw1         = (const float*)d_in[20];
    const float* fb1         = (const float*)d_in[21];
    const float* fw2         = (const float*)d_in[22];
    const float* fb2         = (const float*)d_in[23];
    float* out = (float*)d_out;

    upsample_kernel<<<1024, 256>>>(coords1, up_mask, fte_w1, fte_w2, wk, out);
    decoder_kernel<<<2048, 64>>>(cost_maps, cost_memory, coords1,
                                 fte_b1, fte_b2,
                                 ln1_g, ln1_b, ln2_g, ln2_b,
                                 wq, bq, wv, bv, wp, bp,
                                 fw1, fb1, fw2, fb2, out);
}